// round 5
// baseline (speedup 1.0000x reference)
#include <cuda_runtime.h>
#include <math.h>
#include <stdint.h>

#define MAXN 400000
#define MAXB 10000

// Scratch (static device globals; no allocations)
__device__ float g_w[MAXN];
__device__ float g_ew[MAXN];
__device__ float g_anorm[MAXB];
__device__ float g_bmax[(MAXN + 7) / 8];
__device__ float g_A[256];     // A0[0:128], A1[128:256]
__device__ float g_s[4];       // [0]=s0, [1]=s1, [2]=wmax, [3]=S
__device__ float g_Wr[3][16384];  // tf32-rounded W1, W2, Wo

// shifted softplus: softplus(x) - ln(2)
__device__ __forceinline__ float sspf(float x) {
    float ax = fabsf(x);
    float t = __expf(-ax);
    return fmaxf(x, 0.f) + __logf(1.f + t) - 0.69314718055994531f;
}

// fp32 -> tf32 round-to-nearest (bits)
__device__ __forceinline__ uint32_t tf32r(float x) {
    uint32_t u;
    asm("cvt.rna.tf32.f32 %0, %1;" : "=r"(u) : "f"(x));
    return u;
}

__device__ __forceinline__ uint32_t smem_u32(const void* p) {
    uint32_t a;
    asm("{ .reg .u64 t; cvta.to.shared.u64 t, %1; cvt.u32.u64 %0, t; }" : "=r"(a) : "l"(p));
    return a;
}

// conflict-free swizzled float index into a 128x128 tile
__device__ __forceinline__ int swz(int r, int c) {
    return r * 128 + (c ^ ((r & 7) * 4));
}

__device__ __forceinline__ void cpa16(uint32_t dst, const float* src) {
    asm volatile("cp.async.ca.shared.global [%0], [%1], 16;"
                 :: "r"(dst), "l"(__cvta_generic_to_global(src)) : "memory");
}
#define CP_COMMIT() asm volatile("cp.async.commit_group;" ::: "memory")
#define CP_WAIT1()  asm volatile("cp.async.wait_group 1;" ::: "memory")

__device__ __forceinline__ void mmatf32(float d[4], const uint32_t a[4], const uint32_t b[2]) {
    asm volatile(
        "mma.sync.aligned.m16n8k8.row.col.f32.tf32.tf32.f32 "
        "{%0,%1,%2,%3}, {%4,%5,%6,%7}, {%8,%9}, {%0,%1,%2,%3};"
        : "+f"(d[0]), "+f"(d[1]), "+f"(d[2]), "+f"(d[3])
        : "r"(a[0]), "r"(a[1]), "r"(a[2]), "r"(a[3]), "r"(b[0]), "r"(b[1]));
}

// 128x128x128: warp computes 32x32 tile at (mb, nb). su/sw swizzled smem tiles.
__device__ __forceinline__ void gemm128(const float* __restrict__ su,
                                        const float* __restrict__ sw,
                                        int mb, int nb, int lane,
                                        float acc[2][4][4]) {
#pragma unroll
    for (int mi = 0; mi < 2; mi++)
#pragma unroll
        for (int nf = 0; nf < 4; nf++)
#pragma unroll
            for (int k = 0; k < 4; k++) acc[mi][nf][k] = 0.f;

    const int lq = lane >> 2, lr = lane & 3;
#pragma unroll
    for (int kb = 0; kb < 16; kb++) {
        int k0 = kb * 8 + lr;
        uint32_t a[2][4], b[4][2];
#pragma unroll
        for (int mi = 0; mi < 2; mi++) {
            int r = mb + mi * 16 + lq;
            a[mi][0] = __float_as_uint(su[swz(r, k0)]);
            a[mi][1] = __float_as_uint(su[swz(r + 8, k0)]);
            a[mi][2] = __float_as_uint(su[swz(r, k0 + 4)]);
            a[mi][3] = __float_as_uint(su[swz(r + 8, k0 + 4)]);
        }
#pragma unroll
        for (int nf = 0; nf < 4; nf++) {
            int n = nb + nf * 8 + lq;
            b[nf][0] = __float_as_uint(sw[swz(n, k0)]);
            b[nf][1] = __float_as_uint(sw[swz(n, k0 + 4)]);
        }
#pragma unroll
        for (int mi = 0; mi < 2; mi++)
#pragma unroll
            for (int nf = 0; nf < 4; nf++)
                mmatf32(acc[mi][nf], a[mi], b[nf]);
    }
}

__device__ __forceinline__ void st2u(float* su, int r, int c, uint32_t v0, uint32_t v1) {
    *(uint2*)(su + swz(r, c)) = make_uint2(v0, v1);
}

// issue one 64KB weight tile (swizzled) via cp.async, one commit group
__device__ __forceinline__ void issueW(uint32_t swbase, const float* __restrict__ src, int tid) {
#pragma unroll
    for (int it = 0; it < 8; it++) {
        int t = it * 512 + tid;          // 4096 16B chunks
        int n = t >> 5, k4 = (t & 31) << 2;
        cpa16(swbase + 4u * (uint32_t)swz(n, k4), src + t * 4);
    }
    CP_COMMIT();
}

// ---------------------------------------------------------------------------
// Prologue: tf32-round the three weight matrices once
// ---------------------------------------------------------------------------
__global__ void k_round(const float* __restrict__ W1, const float* __restrict__ W2,
                        const float* __restrict__ Wo) {
    int t = blockIdx.x * 1024 + threadIdx.x;
    if (t < 16384) g_Wr[0][t] = __uint_as_float(tf32r(W1[t]));
    else if (t < 32768) g_Wr[1][t - 16384] = __uint_as_float(tf32r(W2[t - 16384]));
    else if (t < 49152) g_Wr[2][t - 32768] = __uint_as_float(tf32r(Wo[t - 32768]));
}

// ---------------------------------------------------------------------------
// Pre-pass kernels (attention scalar path)
// ---------------------------------------------------------------------------
__global__ void k_prep(const float* __restrict__ Wq, const float* __restrict__ bq,
                       const float* __restrict__ Wk) {
    int j = threadIdx.x;
    float a0 = 0.f, a1 = 0.f;
    for (int f = 0; f < 128; f++) {
        float wq = Wq[f * 128 + j];
        a0 += wq * Wk[2 * f];
        a1 += wq * Wk[2 * f + 1];
    }
    g_A[j] = a0;
    g_A[128 + j] = a1;

    __shared__ float sb[128];
    sb[j] = bq[j] * Wk[2 * j];
    __syncthreads();
    for (int o = 64; o > 0; o >>= 1) {
        if (j < o) sb[j] += sb[j + o];
        __syncthreads();
    }
    if (j == 0) g_s[0] = sb[0];
    __syncthreads();
    sb[j] = bq[j] * Wk[2 * j + 1];
    __syncthreads();
    for (int o = 64; o > 0; o >>= 1) {
        if (j < o) sb[j] += sb[j + o];
        __syncthreads();
    }
    if (j == 0) g_s[1] = sb[0];
}

__global__ void k_w(const float* __restrict__ x, const float* __restrict__ ef,
                    const int* __restrict__ idx, int N) {
    __shared__ float A0s[128], A1s[128];
    __shared__ float wms[8];
    int t = threadIdx.x;
    if (t < 128) A0s[t] = g_A[t];
    else A1s[t - 128] = g_A[t];
    __syncthreads();

    int warp = t >> 5, lane = t & 31;
    int i = blockIdx.x * 8 + warp;
    float wv = -INFINITY;
    if (i < N) {
        int b = idx[i];
        float v = ef[b];
        float e0 = fmaxf(v, 0.f), e1 = fmaxf(-v, 0.f);
        float en0 = e0 / fmaxf(e0, 1.f), en1 = e1 / fmaxf(e1, 1.f);
        float4 xv = ((const float4*)(x + (size_t)i * 128))[lane];
        int j = lane * 4;
        float dot = xv.x * (en0 * A0s[j] + en1 * A1s[j]) +
                    xv.y * (en0 * A0s[j + 1] + en1 * A1s[j + 1]) +
                    xv.z * (en0 * A0s[j + 2] + en1 * A1s[j + 2]) +
                    xv.w * (en0 * A0s[j + 3] + en1 * A1s[j + 3]);
#pragma unroll
        for (int o = 16; o > 0; o >>= 1) dot += __shfl_xor_sync(0xffffffffu, dot, o);
        wv = (dot + en0 * g_s[0] + en1 * g_s[1]) * 0.08838834764831845f;
        if (lane == 0) g_w[i] = wv;
    }
    if (lane == 0) wms[warp] = wv;
    __syncthreads();
    if (t == 0) {
        float m = wms[0];
#pragma unroll
        for (int k = 1; k < 8; k++) m = fmaxf(m, wms[k]);
        g_bmax[blockIdx.x] = m;
    }
}

__global__ void k_max(int nb) {
    __shared__ float sd[1024];
    float m = -INFINITY;
    for (int i = threadIdx.x; i < nb; i += 1024) m = fmaxf(m, g_bmax[i]);
    sd[threadIdx.x] = m;
    __syncthreads();
    for (int o = 512; o > 0; o >>= 1) {
        if (threadIdx.x < o) sd[threadIdx.x] = fmaxf(sd[threadIdx.x], sd[threadIdx.x + o]);
        __syncthreads();
    }
    if (threadIdx.x == 0) g_s[2] = sd[0];
}

__global__ void k_exp(int N) {
    int i = blockIdx.x * blockDim.x + threadIdx.x;
    if (i < N) g_ew[i] = expf(g_w[i] - g_s[2]);
}

__device__ __forceinline__ int lbound(const int* __restrict__ a, int n, int v) {
    int lo = 0, hi = n;
    while (lo < hi) {
        int m = (lo + hi) >> 1;
        if (a[m] < v) lo = m + 1;
        else hi = m;
    }
    return lo;
}

__global__ void k_anorm(const int* __restrict__ idx, int N, int B) {
    int gw = (blockIdx.x * blockDim.x + threadIdx.x) >> 5;
    int lane = threadIdx.x & 31;
    if (gw >= B) return;
    int lo = lbound(idx, N, gw);
    int hi = lbound(idx, N, gw + 1);
    float s = 0.f;
    for (int i = lo + lane; i < hi; i += 32) s += g_ew[i];
#pragma unroll
    for (int o = 16; o > 0; o >>= 1) s += __shfl_xor_sync(0xffffffffu, s, o);
    if (lane == 0) g_anorm[gw] = s;
}

__global__ void k_sum(int B) {
    __shared__ float sd[1024];
    float s = 0.f;
    for (int i = threadIdx.x; i < B; i += 1024) s += g_anorm[i];
    sd[threadIdx.x] = s;
    __syncthreads();
    for (int o = 512; o > 0; o >>= 1) {
        if (threadIdx.x < o) sd[threadIdx.x] += sd[threadIdx.x + o];
        __syncthreads();
    }
    if (threadIdx.x == 0) g_s[3] = sd[0];
}

// ---------------------------------------------------------------------------
// Persistent fused MLP via mma.sync tf32.
// smem floats: su[16384] | w0[16384] | w1[16384] | p[128] q[128] wx[128] wy[128]
// ---------------------------------------------------------------------------
__global__ void __launch_bounds__(512, 1)
k_mlp_mma(const float* __restrict__ ef, const int* __restrict__ idx,
          const float* __restrict__ Wv, float* __restrict__ out,
          int N, int ntiles) {
    extern __shared__ float sm[];
    float* su = sm;
    float* wbuf[2] = {sm + 16384, sm + 32768};
    float* sp = sm + 49152;
    float* sq = sp + 128;
    float* swx = sq + 128;
    float* swy = swx + 128;

    const uint32_t sb = smem_u32(sm);
    const uint32_t wbu[2] = {sb + 16384u * 4u, sb + 32768u * 4u};

    const int tid = threadIdx.x;
    const int lane = tid & 31, wid = tid >> 5;
    const int mb = (wid >> 2) * 32, nb = (wid & 3) * 32;
    const int lq = lane >> 2, lr = lane & 3;

    if (tid < 128) {
        float2 wv = ((const float2*)Wv)[tid];
        swx[tid] = wv.x;
        swy[tid] = wv.y;
    }

    // prologue: W1 -> wbuf[0]
    issueW(wbu[0], g_Wr[0], tid);

    const float Sg = g_s[3];
    int p = 0;
    float acc[2][4][4];

    for (int tile = blockIdx.x; tile < ntiles; tile += gridDim.x) {
        // prefetch W2 -> wbuf[1-p]
        issueW(wbu[1 - p], g_Wr[1], tid);

        // per-row scalars p,q
        if (tid < 128) {
            int i = tile * 128 + tid;
            float pc = 0.f, qc = 0.f;
            if (i < N) {
                int b = idx[i];
                float v = ef[b];
                float c = g_ew[i] / (g_anorm[b] + 1e-8f * Sg);
                pc = c * fmaxf(v, 0.f);
                qc = c * fmaxf(-v, 0.f);
            }
            sp[tid] = pc;
            sq[tid] = qc;
        }
        __syncthreads();

        // stage 0: u = tf32(ssp(x)),  x = p[r]*wx[c] + q[r]*wy[c]
#pragma unroll
        for (int it = 0; it < 8; it++) {
            int f = it * 512 + tid;          // float4 index
            int r = f >> 5, c4 = (f & 31) << 2;
            float pr = sp[r], qr = sq[r];
            uint4 o;
            o.x = tf32r(sspf(pr * swx[c4 + 0] + qr * swy[c4 + 0]));
            o.y = tf32r(sspf(pr * swx[c4 + 1] + qr * swy[c4 + 1]));
            o.z = tf32r(sspf(pr * swx[c4 + 2] + qr * swy[c4 + 2]));
            o.w = tf32r(sspf(pr * swx[c4 + 3] + qr * swy[c4 + 3]));
            *(uint4*)(su + swz(r, c4)) = o;
        }
        CP_WAIT1();   // W1 ready
        __syncthreads();

        // GEMM1: D = u @ W1^T
        gemm128(su, wbuf[p], mb, nb, lane, acc);
        __syncthreads();

        // prefetch Wo -> wbuf[p] (W1 dead)
        issueW(wbu[p], g_Wr[2], tid);

        // epi1: u = tf32(ssp(D))
#pragma unroll
        for (int mi = 0; mi < 2; mi++) {
            int r = mb + mi * 16 + lq;
#pragma unroll
            for (int nf = 0; nf < 4; nf++) {
                int c = nb + nf * 8 + 2 * lr;
                st2u(su, r, c, tf32r(sspf(acc[mi][nf][0])), tf32r(sspf(acc[mi][nf][1])));
                st2u(su, r + 8, c, tf32r(sspf(acc[mi][nf][2])), tf32r(sspf(acc[mi][nf][3])));
            }
        }
        CP_WAIT1();   // W2 ready
        __syncthreads();

        // GEMM2: D = u @ W2^T
        gemm128(su, wbuf[1 - p], mb, nb, lane, acc);
        __syncthreads();

        // prefetch next tile's W1 -> wbuf[1-p] (W2 dead)
        issueW(wbu[1 - p], g_Wr[0], tid);

        // epi2: u = tf32(ssp(x + D)), x regenerated
#pragma unroll
        for (int mi = 0; mi < 2; mi++) {
            int r = mb + mi * 16 + lq;
            float p0 = sp[r], q0 = sq[r];
            float p1 = sp[r + 8], q1 = sq[r + 8];
#pragma unroll
            for (int nf = 0; nf < 4; nf++) {
                int c = nb + nf * 8 + 2 * lr;
                float wxa = swx[c], wxb = swx[c + 1];
                float wya = swy[c], wyb = swy[c + 1];
                st2u(su, r, c,
                     tf32r(sspf(p0 * wxa + q0 * wya + acc[mi][nf][0])),
                     tf32r(sspf(p0 * wxb + q0 * wyb + acc[mi][nf][1])));
                st2u(su, r + 8, c,
                     tf32r(sspf(p1 * wxa + q1 * wya + acc[mi][nf][2])),
                     tf32r(sspf(p1 * wxb + q1 * wyb + acc[mi][nf][3])));
            }
        }
        CP_WAIT1();   // Wo ready
        __syncthreads();

        // GEMM3: D = u @ Wo^T
        gemm128(su, wbuf[p], mb, nb, lane, acc);
        __syncthreads();

        // epi3: stage D through su for coalesced stores
#pragma unroll
        for (int mi = 0; mi < 2; mi++) {
            int r = mb + mi * 16 + lq;
#pragma unroll
            for (int nf = 0; nf < 4; nf++) {
                int c = nb + nf * 8 + 2 * lr;
                *(float2*)(su + swz(r, c)) = make_float2(acc[mi][nf][0], acc[mi][nf][1]);
                *(float2*)(su + swz(r + 8, c)) = make_float2(acc[mi][nf][2], acc[mi][nf][3]);
            }
        }
        __syncthreads();

        // coalesced output: tile rows are contiguous in out
        {
            float* ob = out + (size_t)tile * 128 * 128;
#pragma unroll
            for (int it = 0; it < 8; it++) {
                int f = it * 512 + tid;
                int r = f >> 5, c4 = (f & 31) << 2;
                if (tile * 128 + r < N) {
                    float4 v = *(const float4*)(su + swz(r, c4));
                    *(float4*)(ob + f * 4) = v;
                }
            }
        }
        __syncthreads();
        p ^= 1;
    }
}

// ---------------------------------------------------------------------------
extern "C" void kernel_launch(void* const* d_in, const int* in_sizes, int n_in,
                              void* d_out, int out_size) {
    const float* x   = (const float*)d_in[0];  // input_embedding [N,128]
    const float* ef  = (const float*)d_in[1];  // electronic_feature [B]
    const int*   idx = (const int*)d_in[2];    // idx_m [N]
    const float* Wq  = (const float*)d_in[3];  // [128,128]
    const float* bq  = (const float*)d_in[4];  // [128]
    const float* Wk  = (const float*)d_in[5];  // [128,2]
    const float* Wv  = (const float*)d_in[6];  // [128,2]
    const float* W1  = (const float*)d_in[7];  // [128,128]
    const float* W2  = (const float*)d_in[8];  // [128,128]
    const float* Wo  = (const float*)d_in[9];  // [128,128]
    float* out = (float*)d_out;

    int B = in_sizes[1];
    int N = in_sizes[2];

    k_prep<<<1, 128>>>(Wq, bq, Wk);
    k_round<<<48, 1024>>>(W1, W2, Wo);

    int nb1 = (N + 7) / 8;
    k_w<<<nb1, 256>>>(x, ef, idx, N);
    k_max<<<1, 1024>>>(nb1);
    k_exp<<<(N + 255) / 256, 256>>>(N);
    k_anorm<<<(B + 7) / 8, 256>>>(idx, N, B);
    k_sum<<<1, 1024>>>(B);

    int ntiles = (N + 127) / 128;
    int grid = ntiles < 148 ? ntiles : 148;
    cudaFuncSetAttribute(k_mlp_mma, cudaFuncAttributeMaxDynamicSharedMemorySize, 200704);
    k_mlp_mma<<<grid, 512, 200704>>>(ef, idx, Wv, out, N, ntiles);
}

// round 7
// speedup vs baseline: 2.5303x; 2.5303x over previous
#include <cuda_runtime.h>
#include <math.h>
#include <stdint.h>

#define MAXN 400000
#define MAXB 10000
#define STRIDE 132   // padded row stride (floats) -> conflict-free, k-delta separable

// Scratch (static device globals; no allocations)
__device__ float g_w[MAXN];
__device__ float g_ew[MAXN];
__device__ float g_anorm[MAXB];
__device__ float g_bmax[(MAXN + 7) / 8];
__device__ float g_A[256];        // A0[0:128], A1[128:256]
__device__ float g_s[4];          // [0]=s0, [1]=s1
__device__ float g_Wr[3][16384];  // tf32-rounded W1, W2, Wo

__device__ __forceinline__ float sspf(float x) {
    float ax = fabsf(x);
    float t = __expf(-ax);
    return fmaxf(x, 0.f) + __logf(1.f + t) - 0.69314718055994531f;
}

__device__ __forceinline__ uint32_t tf32r(float x) {
    uint32_t u;
    asm("cvt.rna.tf32.f32 %0, %1;" : "=r"(u) : "f"(x));
    return u;
}

__device__ __forceinline__ void cpa16(uint32_t dst, const float* src) {
    asm volatile("cp.async.ca.shared.global [%0], [%1], 16;"
                 :: "r"(dst), "l"(__cvta_generic_to_global(src)) : "memory");
}
#define CP_COMMIT() asm volatile("cp.async.commit_group;" ::: "memory")
#define CP_WAIT1()  asm volatile("cp.async.wait_group 1;" ::: "memory")

__device__ __forceinline__ uint32_t smem_u32(const void* p) {
    uint32_t a;
    asm("{ .reg .u64 t; cvta.to.shared.u64 t, %1; cvt.u32.u64 %0, t; }" : "=r"(a) : "l"(p));
    return a;
}

__device__ __forceinline__ void mmatf32(float d[4], const uint32_t a[4], const uint32_t b[2]) {
    asm volatile(
        "mma.sync.aligned.m16n8k8.row.col.f32.tf32.tf32.f32 "
        "{%0,%1,%2,%3}, {%4,%5,%6,%7}, {%8,%9}, {%0,%1,%2,%3};"
        : "+f"(d[0]), "+f"(d[1]), "+f"(d[2]), "+f"(d[3])
        : "r"(a[0]), "r"(a[1]), "r"(a[2]), "r"(a[3]), "r"(b[0]), "r"(b[1]));
}

// 128x128x128 GEMM, warp tile 32x32 at (mb, nb). Padded-layout tiles.
// All k-offsets are compile-time immediates off 3 base pointers.
__device__ __forceinline__ void gemm128(const float* __restrict__ su,
                                        const float* __restrict__ sw,
                                        int mb, int nb, int lane,
                                        float acc[2][4][4]) {
#pragma unroll
    for (int mi = 0; mi < 2; mi++)
#pragma unroll
        for (int nf = 0; nf < 4; nf++)
#pragma unroll
            for (int k = 0; k < 4; k++) acc[mi][nf][k] = 0.f;

    const int lq = lane >> 2, lr = lane & 3;
    const float* a0 = su + (mb + lq) * STRIDE + lr;
    const float* a1 = a0 + 16 * STRIDE;
    const float* b0 = sw + (nb + lq) * STRIDE + lr;

#pragma unroll
    for (int kb = 0; kb < 16; kb++) {
        const int k8 = kb * 8;
        uint32_t a[2][4], b[4][2];
        a[0][0] = __float_as_uint(a0[k8]);
        a[0][1] = __float_as_uint(a0[8 * STRIDE + k8]);
        a[0][2] = __float_as_uint(a0[k8 + 4]);
        a[0][3] = __float_as_uint(a0[8 * STRIDE + k8 + 4]);
        a[1][0] = __float_as_uint(a1[k8]);
        a[1][1] = __float_as_uint(a1[8 * STRIDE + k8]);
        a[1][2] = __float_as_uint(a1[k8 + 4]);
        a[1][3] = __float_as_uint(a1[8 * STRIDE + k8 + 4]);
#pragma unroll
        for (int nf = 0; nf < 4; nf++) {
            b[nf][0] = __float_as_uint(b0[nf * 8 * STRIDE + k8]);
            b[nf][1] = __float_as_uint(b0[nf * 8 * STRIDE + k8 + 4]);
        }
#pragma unroll
        for (int mi = 0; mi < 2; mi++)
#pragma unroll
            for (int nf = 0; nf < 4; nf++)
                mmatf32(acc[mi][nf], a[mi], b[nf]);
    }
}

// issue one weight tile (padded layout) via cp.async, one commit group
__device__ __forceinline__ void issueW(uint32_t swbase, const float* __restrict__ src, int tid) {
#pragma unroll
    for (int it = 0; it < 8; it++) {
        int t = it * 512 + tid;             // 4096 16B chunks
        int n = t >> 5, k4 = (t & 31) << 2;
        cpa16(swbase + 4u * (uint32_t)(n * STRIDE + k4), src + t * 4);
    }
    CP_COMMIT();
}

// ---------------------------------------------------------------------------
// Launch 1: fused prep (A0/A1/s0/s1) + tf32-round of W1/W2/Wo.
// Block 0 does prep with no __syncthreads (warp-local reductions);
// blocks 1..48 round the weights.
// ---------------------------------------------------------------------------
__global__ void k_prep_round(const float* __restrict__ Wq, const float* __restrict__ bq,
                             const float* __restrict__ Wk,
                             const float* __restrict__ W1, const float* __restrict__ W2,
                             const float* __restrict__ Wo) {
    if (blockIdx.x == 0) {
        int j = threadIdx.x;
        if (j < 128) {
            float a0 = 0.f, a1 = 0.f;
            for (int f = 0; f < 128; f++) {
                float wq = Wq[f * 128 + j];
                a0 += wq * Wk[2 * f];
                a1 += wq * Wk[2 * f + 1];
            }
            g_A[j] = a0;
            g_A[128 + j] = a1;
        }
        int wid = threadIdx.x >> 5, lane = threadIdx.x & 31;
        if (wid < 2) {
            float s = 0.f;
            for (int l = lane; l < 128; l += 32) s += bq[l] * Wk[2 * l + wid];
#pragma unroll
            for (int o = 16; o > 0; o >>= 1) s += __shfl_xor_sync(0xffffffffu, s, o);
            if (lane == 0) g_s[wid] = s;
        }
    } else {
        int t = (blockIdx.x - 1) * 1024 + threadIdx.x;
        if (t < 16384) g_Wr[0][t] = __uint_as_float(tf32r(W1[t]));
        else if (t < 32768) g_Wr[1][t - 16384] = __uint_as_float(tf32r(W2[t - 16384]));
        else g_Wr[2][t - 32768] = __uint_as_float(tf32r(Wo[t - 32768]));
    }
}

// ---------------------------------------------------------------------------
// Launch 2: w[i] + per-block max
// ---------------------------------------------------------------------------
__global__ void k_w(const float* __restrict__ x, const float* __restrict__ ef,
                    const int* __restrict__ idx, int N) {
    __shared__ float A0s[128], A1s[128];
    __shared__ float wms[8];
    int t = threadIdx.x;
    if (t < 128) A0s[t] = g_A[t];
    else A1s[t - 128] = g_A[t];
    __syncthreads();

    int warp = t >> 5, lane = t & 31;
    int i = blockIdx.x * 8 + warp;
    float wv = -INFINITY;
    if (i < N) {
        int b = idx[i];
        float v = ef[b];
        float e0 = fmaxf(v, 0.f), e1 = fmaxf(-v, 0.f);
        float en0 = e0 / fmaxf(e0, 1.f), en1 = e1 / fmaxf(e1, 1.f);
        float4 xv = ((const float4*)(x + (size_t)i * 128))[lane];
        int j = lane * 4;
        float dot = xv.x * (en0 * A0s[j] + en1 * A1s[j]) +
                    xv.y * (en0 * A0s[j + 1] + en1 * A1s[j + 1]) +
                    xv.z * (en0 * A0s[j + 2] + en1 * A1s[j + 2]) +
                    xv.w * (en0 * A0s[j + 3] + en1 * A1s[j + 3]);
#pragma unroll
        for (int o = 16; o > 0; o >>= 1) dot += __shfl_xor_sync(0xffffffffu, dot, o);
        wv = (dot + en0 * g_s[0] + en1 * g_s[1]) * 0.08838834764831845f;
        if (lane == 0) g_w[i] = wv;
    }
    if (lane == 0) wms[warp] = wv;
    __syncthreads();
    if (t == 0) {
        float m = wms[0];
#pragma unroll
        for (int k = 1; k < 8; k++) m = fmaxf(m, wms[k]);
        g_bmax[blockIdx.x] = m;
    }
}

// ---------------------------------------------------------------------------
// Launch 3: fused global-max (redundant per-block scan of g_bmax) +
//           ew=exp(w-max) + per-molecule segment sums. 32 molecules/block.
// ---------------------------------------------------------------------------
__device__ __forceinline__ int lbound(const int* __restrict__ a, int n, int v) {
    int lo = 0, hi = n;
    while (lo < hi) {
        int m = (lo + hi) >> 1;
        if (a[m] < v) lo = m + 1;
        else hi = m;
    }
    return lo;
}

__global__ void k_soft(const int* __restrict__ idx, int N, int B, int nb) {
    __shared__ float sd[1024];
    float m = -INFINITY;
    for (int i = threadIdx.x; i < nb; i += 1024) m = fmaxf(m, g_bmax[i]);
    sd[threadIdx.x] = m;
    __syncthreads();
    for (int o = 512; o > 0; o >>= 1) {
        if (threadIdx.x < o) sd[threadIdx.x] = fmaxf(sd[threadIdx.x], sd[threadIdx.x + o]);
        __syncthreads();
    }
    const float wmax = sd[0];

    int warp = threadIdx.x >> 5, lane = threadIdx.x & 31;
    int gw = blockIdx.x * 32 + warp;
    if (gw >= B) return;
    int lo = lbound(idx, N, gw);
    int hi = lbound(idx, N, gw + 1);
    float s = 0.f;
    for (int i = lo + lane; i < hi; i += 32) {
        float e = expf(g_w[i] - wmax);
        g_ew[i] = e;
        s += e;
    }
#pragma unroll
    for (int o = 16; o > 0; o >>= 1) s += __shfl_xor_sync(0xffffffffu, s, o);
    if (lane == 0) g_anorm[gw] = s;
}

// ---------------------------------------------------------------------------
// Launch 4: persistent fused MLP via mma.sync tf32 (padded smem layout).
// smem floats: su[128*132] | w0[128*132] | w1[128*132] | sp[128] sq[128] swx[128] swy[128]
// ---------------------------------------------------------------------------
__global__ void __launch_bounds__(512, 1)
k_mlp_mma(const float* __restrict__ ef, const int* __restrict__ idx,
          const float* __restrict__ Wv, float* __restrict__ out,
          int N, int B, int ntiles) {
    extern __shared__ float sm[];
    const int TSZ = 128 * STRIDE;  // 16896
    float* su = sm;
    float* wbuf[2] = {sm + TSZ, sm + 2 * TSZ};
    float* sp = sm + 3 * TSZ;
    float* sq = sp + 128;
    float* swx = sq + 128;
    float* swy = swx + 128;
    float* sred = swy + 128;  // 16 floats for S reduction

    const uint32_t sb = smem_u32(sm);
    const uint32_t wbu[2] = {sb + (uint32_t)TSZ * 4u, sb + (uint32_t)TSZ * 8u};

    const int tid = threadIdx.x;
    const int lane = tid & 31, wid = tid >> 5;
    const int mb = (wid >> 2) * 32, nb = (wid & 3) * 32;
    const int lq = lane >> 2, lr = lane & 3;

    if (tid < 128) {
        float2 wv = ((const float2*)Wv)[tid];
        swx[tid] = wv.x;
        swy[tid] = wv.y;
    }

    // deterministic per-CTA sum S = sum(anorm)
    {
        float s = 0.f;
        for (int i = tid; i < B; i += 512) s += g_anorm[i];
#pragma unroll
        for (int o = 16; o > 0; o >>= 1) s += __shfl_xor_sync(0xffffffffu, s, o);
        if (lane == 0) sred[wid] = s;
    }
    __syncthreads();
    float Sg = 0.f;
#pragma unroll
    for (int k = 0; k < 16; k++) Sg += sred[k];
    const float epsS = 1e-8f * Sg;

    // prologue: W1 -> wbuf[0]
    issueW(wbu[0], g_Wr[0], tid);

    int p = 0;
    float acc[2][4][4];

    for (int tile = blockIdx.x; tile < ntiles; tile += gridDim.x) {
        issueW(wbu[1 - p], g_Wr[1], tid);  // prefetch W2

        if (tid < 128) {
            int i = tile * 128 + tid;
            float pc = 0.f, qc = 0.f;
            if (i < N) {
                int b = idx[i];
                float v = ef[b];
                float c = g_ew[i] / (g_anorm[b] + epsS);
                pc = c * fmaxf(v, 0.f);
                qc = c * fmaxf(-v, 0.f);
            }
            sp[tid] = pc;
            sq[tid] = qc;
        }
        __syncthreads();

        // stage 0: u = tf32(ssp(x)),  x = p[r]*wx[c] + q[r]*wy[c]
#pragma unroll
        for (int it = 0; it < 8; it++) {
            int f = it * 512 + tid;
            int r = f >> 5, c4 = (f & 31) << 2;
            float pr = sp[r], qr = sq[r];
            uint4 o;
            o.x = tf32r(sspf(pr * swx[c4 + 0] + qr * swy[c4 + 0]));
            o.y = tf32r(sspf(pr * swx[c4 + 1] + qr * swy[c4 + 1]));
            o.z = tf32r(sspf(pr * swx[c4 + 2] + qr * swy[c4 + 2]));
            o.w = tf32r(sspf(pr * swx[c4 + 3] + qr * swy[c4 + 3]));
            *(uint4*)(su + r * STRIDE + c4) = o;
        }
        CP_WAIT1();  // W1 ready
        __syncthreads();

        // GEMM1: D = u @ W1^T
        gemm128(su, wbuf[p], mb, nb, lane, acc);
        __syncthreads();

        issueW(wbu[p], g_Wr[2], tid);  // prefetch Wo (W1 dead)

        // epi1: u = tf32(ssp(D))
#pragma unroll
        for (int mi = 0; mi < 2; mi++) {
            int r = mb + mi * 16 + lq;
#pragma unroll
            for (int nf = 0; nf < 4; nf++) {
                int c = nb + nf * 8 + 2 * lr;
                *(uint2*)(su + r * STRIDE + c) =
                    make_uint2(tf32r(sspf(acc[mi][nf][0])), tf32r(sspf(acc[mi][nf][1])));
                *(uint2*)(su + (r + 8) * STRIDE + c) =
                    make_uint2(tf32r(sspf(acc[mi][nf][2])), tf32r(sspf(acc[mi][nf][3])));
            }
        }
        CP_WAIT1();  // W2 ready
        __syncthreads();

        // GEMM2: D = u @ W2^T
        gemm128(su, wbuf[1 - p], mb, nb, lane, acc);
        __syncthreads();

        issueW(wbu[1 - p], g_Wr[0], tid);  // prefetch next tile's W1 (W2 dead)

        // epi2: u = tf32(ssp(x + D)), x regenerated
#pragma unroll
        for (int mi = 0; mi < 2; mi++) {
            int r = mb + mi * 16 + lq;
            float p0 = sp[r], q0 = sq[r];
            float p1 = sp[r + 8], q1 = sq[r + 8];
#pragma unroll
            for (int nf = 0; nf < 4; nf++) {
                int c = nb + nf * 8 + 2 * lr;
                float wxa = swx[c], wxb = swx[c + 1];
                float wya = swy[c], wyb = swy[c + 1];
                *(uint2*)(su + r * STRIDE + c) = make_uint2(
                    tf32r(sspf(p0 * wxa + q0 * wya + acc[mi][nf][0])),
                    tf32r(sspf(p0 * wxb + q0 * wyb + acc[mi][nf][1])));
                *(uint2*)(su + (r + 8) * STRIDE + c) = make_uint2(
                    tf32r(sspf(p1 * wxa + q1 * wya + acc[mi][nf][2])),
                    tf32r(sspf(p1 * wxb + q1 * wyb + acc[mi][nf][3])));
            }
        }
        CP_WAIT1();  // Wo ready
        __syncthreads();

        // GEMM3: D = u @ Wo^T
        gemm128(su, wbuf[p], mb, nb, lane, acc);
        __syncthreads();

        // stage result through su for coalesced stores
#pragma unroll
        for (int mi = 0; mi < 2; mi++) {
            int r = mb + mi * 16 + lq;
#pragma unroll
            for (int nf = 0; nf < 4; nf++) {
                int c = nb + nf * 8 + 2 * lr;
                *(float2*)(su + r * STRIDE + c) = make_float2(acc[mi][nf][0], acc[mi][nf][1]);
                *(float2*)(su + (r + 8) * STRIDE + c) = make_float2(acc[mi][nf][2], acc[mi][nf][3]);
            }
        }
        __syncthreads();

        {
            float* ob = out + (size_t)tile * 128 * 128;
#pragma unroll
            for (int it = 0; it < 8; it++) {
                int f = it * 512 + tid;
                int r = f >> 5, c4 = (f & 31) << 2;
                if (tile * 128 + r < N) {
                    float4 v = *(const float4*)(su + r * STRIDE + c4);
                    *(float4*)(ob + f * 4) = v;
                }
            }
        }
        __syncthreads();
        p ^= 1;
    }
}

// ---------------------------------------------------------------------------
extern "C" void kernel_launch(void* const* d_in, const int* in_sizes, int n_in,
                              void* d_out, int out_size) {
    const float* x   = (const float*)d_in[0];
    const float* ef  = (const float*)d_in[1];
    const int*   idx = (const int*)d_in[2];
    const float* Wq  = (const float*)d_in[3];
    const float* bq  = (const float*)d_in[4];
    const float* Wk  = (const float*)d_in[5];
    const float* Wv  = (const float*)d_in[6];
    const float* W1  = (const float*)d_in[7];
    const float* W2  = (const float*)d_in[8];
    const float* Wo  = (const float*)d_in[9];
    float* out = (float*)d_out;

    int B = in_sizes[1];
    int N = in_sizes[2];

    k_prep_round<<<49, 1024>>>(Wq, bq, Wk, W1, W2, Wo);

    int nb1 = (N + 7) / 8;
    k_w<<<nb1, 256>>>(x, ef, idx, N);
    k_soft<<<(B + 31) / 32, 1024>>>(idx, N, B, nb1);

    int ntiles = (N + 127) / 128;
    int grid = ntiles < 148 ? ntiles : 148;
    int smem = (3 * 128 * STRIDE + 4 * 128 + 16) * 4;
    cudaFuncSetAttribute(k_mlp_mma, cudaFuncAttributeMaxDynamicSharedMemorySize, smem);
    k_mlp_mma<<<grid, 512, smem>>>(ef, idx, Wv, out, N, B, ntiles);
}

// round 8
// speedup vs baseline: 3.0460x; 1.2038x over previous
#include <cuda_runtime.h>
#include <math.h>
#include <stdint.h>

#define MAXN 400000
#define MAXB 10000
#define STRIDE 132   // padded row stride (floats) -> conflict-free fragment LDS

// Scratch (static device globals; no allocations)
__device__ float g_w[MAXN];
__device__ float g_ew[MAXN];
__device__ float g_anorm[MAXB];
__device__ float g_bmax[(MAXN + 7) / 8];
__device__ float g_A[256];        // A0[0:128], A1[128:256]
__device__ float g_s[4];          // [0]=s0, [1]=s1
__device__ float g_Wr[3][16384];  // tf32-rounded W1, W2, Wo

__device__ __forceinline__ float sspf(float x) {
    float ax = fabsf(x);
    float t = __expf(-ax);
    return fmaxf(x, 0.f) + __logf(1.f + t) - 0.69314718055994531f;
}

__device__ __forceinline__ uint32_t tf32r(float x) {
    uint32_t u;
    asm("cvt.rna.tf32.f32 %0, %1;" : "=r"(u) : "f"(x));
    return u;
}

__device__ __forceinline__ void cpa16(uint32_t dst, const float* src) {
    asm volatile("cp.async.ca.shared.global [%0], [%1], 16;"
                 :: "r"(dst), "l"(__cvta_generic_to_global(src)) : "memory");
}
#define CP_COMMIT() asm volatile("cp.async.commit_group;" ::: "memory")
#define CP_WAIT0()  asm volatile("cp.async.wait_group 0;" ::: "memory")

__device__ __forceinline__ uint32_t smem_u32(const void* p) {
    uint32_t a;
    asm("{ .reg .u64 t; cvta.to.shared.u64 t, %1; cvt.u32.u64 %0, t; }" : "=r"(a) : "l"(p));
    return a;
}

__device__ __forceinline__ void mmatf32(float d[4], const uint32_t a[4], const uint32_t b[2]) {
    asm volatile(
        "mma.sync.aligned.m16n8k8.row.col.f32.tf32.tf32.f32 "
        "{%0,%1,%2,%3}, {%4,%5,%6,%7}, {%8,%9}, {%0,%1,%2,%3};"
        : "+f"(d[0]), "+f"(d[1]), "+f"(d[2]), "+f"(d[3])
        : "r"(a[0]), "r"(a[1]), "r"(a[2]), "r"(a[3]), "r"(b[0]), "r"(b[1]));
}

// 256x128x128 GEMM phase: warp computes 64x32 tile at (mb, nb).
// su: 256xSTRIDE activations; sw: 128xSTRIDE weights. All k-offsets immediate.
__device__ __forceinline__ void gemm256(const float* __restrict__ su,
                                        const float* __restrict__ sw,
                                        int mb, int nb, int lane,
                                        float acc[4][4][4]) {
#pragma unroll
    for (int mf = 0; mf < 4; mf++)
#pragma unroll
        for (int nf = 0; nf < 4; nf++)
#pragma unroll
            for (int k = 0; k < 4; k++) acc[mf][nf][k] = 0.f;

    const int lq = lane >> 2, lr = lane & 3;
    const float* a0 = su + (mb + lq) * STRIDE + lr;
    const float* b0 = sw + (nb + lq) * STRIDE + lr;

#pragma unroll
    for (int kb = 0; kb < 16; kb++) {
        const int k8 = kb * 8;
        uint32_t a[4][4], b[4][2];
#pragma unroll
        for (int mf = 0; mf < 4; mf++) {
            const float* ap = a0 + mf * 16 * STRIDE;
            a[mf][0] = __float_as_uint(ap[k8]);
            a[mf][1] = __float_as_uint(ap[8 * STRIDE + k8]);
            a[mf][2] = __float_as_uint(ap[k8 + 4]);
            a[mf][3] = __float_as_uint(ap[8 * STRIDE + k8 + 4]);
        }
#pragma unroll
        for (int nf = 0; nf < 4; nf++) {
            b[nf][0] = __float_as_uint(b0[nf * 8 * STRIDE + k8]);
            b[nf][1] = __float_as_uint(b0[nf * 8 * STRIDE + k8 + 4]);
        }
#pragma unroll
        for (int mf = 0; mf < 4; mf++)
#pragma unroll
            for (int nf = 0; nf < 4; nf++)
                mmatf32(acc[mf][nf], a[mf], b[nf]);
    }
}

// issue one 128x128 weight tile (padded layout) via cp.async, one commit group
__device__ __forceinline__ void issueW(uint32_t swbase, const float* __restrict__ src, int tid) {
#pragma unroll
    for (int it = 0; it < 8; it++) {
        int t = it * 512 + tid;             // 4096 16B chunks
        int n = t >> 5, k4 = (t & 31) << 2;
        cpa16(swbase + 4u * (uint32_t)(n * STRIDE + k4), src + t * 4);
    }
    CP_COMMIT();
}

// ---------------------------------------------------------------------------
// Launch 1: fused prep (A0/A1/s0/s1) + tf32-round of W1/W2/Wo.
// ---------------------------------------------------------------------------
__global__ void k_prep_round(const float* __restrict__ Wq, const float* __restrict__ bq,
                             const float* __restrict__ Wk,
                             const float* __restrict__ W1, const float* __restrict__ W2,
                             const float* __restrict__ Wo) {
    if (blockIdx.x == 0) {
        int j = threadIdx.x;
        if (j < 128) {
            float a0 = 0.f, a1 = 0.f;
            for (int f = 0; f < 128; f++) {
                float wq = Wq[f * 128 + j];
                a0 += wq * Wk[2 * f];
                a1 += wq * Wk[2 * f + 1];
            }
            g_A[j] = a0;
            g_A[128 + j] = a1;
        }
        int wid = threadIdx.x >> 5, lane = threadIdx.x & 31;
        if (wid < 2) {
            float s = 0.f;
            for (int l = lane; l < 128; l += 32) s += bq[l] * Wk[2 * l + wid];
#pragma unroll
            for (int o = 16; o > 0; o >>= 1) s += __shfl_xor_sync(0xffffffffu, s, o);
            if (lane == 0) g_s[wid] = s;
        }
    } else {
        int t = (blockIdx.x - 1) * 1024 + threadIdx.x;
        if (t < 16384) g_Wr[0][t] = __uint_as_float(tf32r(W1[t]));
        else if (t < 32768) g_Wr[1][t - 16384] = __uint_as_float(tf32r(W2[t - 16384]));
        else g_Wr[2][t - 32768] = __uint_as_float(tf32r(Wo[t - 32768]));
    }
}

// ---------------------------------------------------------------------------
// Launch 2: w[i] + per-block max
// ---------------------------------------------------------------------------
__global__ void k_w(const float* __restrict__ x, const float* __restrict__ ef,
                    const int* __restrict__ idx, int N) {
    __shared__ float A0s[128], A1s[128];
    __shared__ float wms[8];
    int t = threadIdx.x;
    if (t < 128) A0s[t] = g_A[t];
    else A1s[t - 128] = g_A[t];
    __syncthreads();

    int warp = t >> 5, lane = t & 31;
    int i = blockIdx.x * 8 + warp;
    float wv = -INFINITY;
    if (i < N) {
        int b = idx[i];
        float v = ef[b];
        float e0 = fmaxf(v, 0.f), e1 = fmaxf(-v, 0.f);
        float en0 = e0 / fmaxf(e0, 1.f), en1 = e1 / fmaxf(e1, 1.f);
        float4 xv = ((const float4*)(x + (size_t)i * 128))[lane];
        int j = lane * 4;
        float dot = xv.x * (en0 * A0s[j] + en1 * A1s[j]) +
                    xv.y * (en0 * A0s[j + 1] + en1 * A1s[j + 1]) +
                    xv.z * (en0 * A0s[j + 2] + en1 * A1s[j + 2]) +
                    xv.w * (en0 * A0s[j + 3] + en1 * A1s[j + 3]);
#pragma unroll
        for (int o = 16; o > 0; o >>= 1) dot += __shfl_xor_sync(0xffffffffu, dot, o);
        wv = (dot + en0 * g_s[0] + en1 * g_s[1]) * 0.08838834764831845f;
        if (lane == 0) g_w[i] = wv;
    }
    if (lane == 0) wms[warp] = wv;
    __syncthreads();
    if (t == 0) {
        float m = wms[0];
#pragma unroll
        for (int k = 1; k < 8; k++) m = fmaxf(m, wms[k]);
        g_bmax[blockIdx.x] = m;
    }
}

// ---------------------------------------------------------------------------
// Launch 3: fused global-max + ew=exp(w-max) + per-molecule segment sums.
// ---------------------------------------------------------------------------
__device__ __forceinline__ int lbound(const int* __restrict__ a, int n, int v) {
    int lo = 0, hi = n;
    while (lo < hi) {
        int m = (lo + hi) >> 1;
        if (a[m] < v) lo = m + 1;
        else hi = m;
    }
    return lo;
}

__global__ void k_soft(const int* __restrict__ idx, int N, int B, int nb) {
    __shared__ float sd[1024];
    float m = -INFINITY;
    for (int i = threadIdx.x; i < nb; i += 1024) m = fmaxf(m, g_bmax[i]);
    sd[threadIdx.x] = m;
    __syncthreads();
    for (int o = 512; o > 0; o >>= 1) {
        if (threadIdx.x < o) sd[threadIdx.x] = fmaxf(sd[threadIdx.x], sd[threadIdx.x + o]);
        __syncthreads();
    }
    const float wmax = sd[0];

    int warp = threadIdx.x >> 5, lane = threadIdx.x & 31;
    int gw = blockIdx.x * 32 + warp;
    if (gw >= B) return;
    int lo = lbound(idx, N, gw);
    int hi = lbound(idx, N, gw + 1);
    float s = 0.f;
    for (int i = lo + lane; i < hi; i += 32) {
        float e = expf(g_w[i] - wmax);
        g_ew[i] = e;
        s += e;
    }
#pragma unroll
    for (int o = 16; o > 0; o >>= 1) s += __shfl_xor_sync(0xffffffffu, s, o);
    if (lane == 0) g_anorm[gw] = s;
}

// ---------------------------------------------------------------------------
// Launch 4: persistent fused MLP, 256-row double tile, mma.sync tf32.
// smem floats: su[256*132] | wbuf[128*132] | sp[256] sq[256] swx[128] swy[128] sred[16]
// ---------------------------------------------------------------------------
__global__ void __launch_bounds__(512, 1)
k_mlp_mma(const float* __restrict__ ef, const int* __restrict__ idx,
          const float* __restrict__ Wv, float* __restrict__ out,
          int N, int B, int niter) {
    extern __shared__ float sm[];
    const int SUSZ = 256 * STRIDE;       // 33792
    const int WSZ = 128 * STRIDE;        // 16896
    float* su = sm;
    float* wbuf = sm + SUSZ;
    float* sp = sm + SUSZ + WSZ;
    float* sq = sp + 256;
    float* swx = sq + 256;
    float* swy = swx + 128;
    float* sred = swy + 128;

    const uint32_t sb = smem_u32(sm);
    const uint32_t wbu = sb + (uint32_t)SUSZ * 4u;

    const int tid = threadIdx.x;
    const int lane = tid & 31, wid = tid >> 5;
    const int mb = (wid >> 2) * 64, nb = (wid & 3) * 32;
    const int lq = lane >> 2, lr = lane & 3;

    if (tid < 128) {
        float2 wv = ((const float2*)Wv)[tid];
        swx[tid] = wv.x;
        swy[tid] = wv.y;
    }

    // deterministic per-CTA sum S = sum(anorm)
    {
        float s = 0.f;
        for (int i = tid; i < B; i += 512) s += g_anorm[i];
#pragma unroll
        for (int o = 16; o > 0; o >>= 1) s += __shfl_xor_sync(0xffffffffu, s, o);
        if (lane == 0) sred[wid] = s;
    }
    __syncthreads();
    float Sg = 0.f;
#pragma unroll
    for (int k = 0; k < 16; k++) Sg += sred[k];
    const float epsS = 1e-8f * Sg;

    // prologue: W1 -> wbuf
    issueW(wbu, g_Wr[0], tid);

    float acc[4][4][4];

    for (int iter = blockIdx.x; iter < niter; iter += gridDim.x) {
        const int row0 = iter * 256;

        // per-row scalars for 256 rows
        if (tid < 256) {
            int i = row0 + tid;
            float pc = 0.f, qc = 0.f;
            if (i < N) {
                int b = idx[i];
                float v = ef[b];
                float c = g_ew[i] / (g_anorm[b] + epsS);
                pc = c * fmaxf(v, 0.f);
                qc = c * fmaxf(-v, 0.f);
            }
            sp[tid] = pc;
            sq[tid] = qc;
        }
        __syncthreads();

        // stage 0: u = tf32(ssp(x)), 256x128
#pragma unroll
        for (int it = 0; it < 16; it++) {
            int f = it * 512 + tid;
            int r = f >> 5, c4 = (f & 31) << 2;
            float pr = sp[r], qr = sq[r];
            uint4 o;
            o.x = tf32r(sspf(pr * swx[c4 + 0] + qr * swy[c4 + 0]));
            o.y = tf32r(sspf(pr * swx[c4 + 1] + qr * swy[c4 + 1]));
            o.z = tf32r(sspf(pr * swx[c4 + 2] + qr * swy[c4 + 2]));
            o.w = tf32r(sspf(pr * swx[c4 + 3] + qr * swy[c4 + 3]));
            *(uint4*)(su + r * STRIDE + c4) = o;
        }
        CP_WAIT0();  // W1 ready
        __syncthreads();

        // GEMM1: D = u @ W1^T
        gemm256(su, wbuf, mb, nb, lane, acc);
        __syncthreads();

        issueW(wbu, g_Wr[1], tid);  // prefetch W2 (overlaps epi1)

        // epi1: u = tf32(ssp(D))
#pragma unroll
        for (int mf = 0; mf < 4; mf++) {
            int r = mb + mf * 16 + lq;
#pragma unroll
            for (int nf = 0; nf < 4; nf++) {
                int c = nb + nf * 8 + 2 * lr;
                *(uint2*)(su + r * STRIDE + c) =
                    make_uint2(tf32r(sspf(acc[mf][nf][0])), tf32r(sspf(acc[mf][nf][1])));
                *(uint2*)(su + (r + 8) * STRIDE + c) =
                    make_uint2(tf32r(sspf(acc[mf][nf][2])), tf32r(sspf(acc[mf][nf][3])));
            }
        }
        CP_WAIT0();  // W2 ready
        __syncthreads();

        // GEMM2: D = u @ W2^T
        gemm256(su, wbuf, mb, nb, lane, acc);
        __syncthreads();

        issueW(wbu, g_Wr[2], tid);  // prefetch Wo (overlaps epi2)

        // epi2: u = tf32(ssp(x + D)), x regenerated
#pragma unroll
        for (int mf = 0; mf < 4; mf++) {
            int r = mb + mf * 16 + lq;
            float p0 = sp[r], q0 = sq[r];
            float p1 = sp[r + 8], q1 = sq[r + 8];
#pragma unroll
            for (int nf = 0; nf < 4; nf++) {
                int c = nb + nf * 8 + 2 * lr;
                float wxa = swx[c], wxb = swx[c + 1];
                float wya = swy[c], wyb = swy[c + 1];
                *(uint2*)(su + r * STRIDE + c) = make_uint2(
                    tf32r(sspf(p0 * wxa + q0 * wya + acc[mf][nf][0])),
                    tf32r(sspf(p0 * wxb + q0 * wyb + acc[mf][nf][1])));
                *(uint2*)(su + (r + 8) * STRIDE + c) = make_uint2(
                    tf32r(sspf(p1 * wxa + q1 * wya + acc[mf][nf][2])),
                    tf32r(sspf(p1 * wxb + q1 * wyb + acc[mf][nf][3])));
            }
        }
        CP_WAIT0();  // Wo ready
        __syncthreads();

        // GEMM3: D = u @ Wo^T
        gemm256(su, wbuf, mb, nb, lane, acc);

        // prefetch next iteration's W1 (wbuf free after this point for all
        // warps only after a sync; the loop-end sync below orders it)
        __syncthreads();
        issueW(wbu, g_Wr[0], tid);

        // direct global stores (32B sector-aligned float2 bursts)
#pragma unroll
        for (int mf = 0; mf < 4; mf++) {
            int r = row0 + mb + mf * 16 + lq;
#pragma unroll
            for (int nf = 0; nf < 4; nf++) {
                int c = nb + nf * 8 + 2 * lr;
                if (r < N)
                    *(float2*)(out + (size_t)r * 128 + c) =
                        make_float2(acc[mf][nf][0], acc[mf][nf][1]);
                if (r + 8 < N)
                    *(float2*)(out + (size_t)(r + 8) * 128 + c) =
                        make_float2(acc[mf][nf][2], acc[mf][nf][3]);
            }
        }
        __syncthreads();  // su safe to overwrite next iteration
    }
}

// ---------------------------------------------------------------------------
extern "C" void kernel_launch(void* const* d_in, const int* in_sizes, int n_in,
                              void* d_out, int out_size) {
    const float* x   = (const float*)d_in[0];
    const float* ef  = (const float*)d_in[1];
    const int*   idx = (const int*)d_in[2];
    const float* Wq  = (const float*)d_in[3];
    const float* bq  = (const float*)d_in[4];
    const float* Wk  = (const float*)d_in[5];
    const float* Wv  = (const float*)d_in[6];
    const float* W1  = (const float*)d_in[7];
    const float* W2  = (const float*)d_in[8];
    const float* Wo  = (const float*)d_in[9];
    float* out = (float*)d_out;

    int B = in_sizes[1];
    int N = in_sizes[2];

    k_prep_round<<<49, 1024>>>(Wq, bq, Wk, W1, W2, Wo);

    int nb1 = (N + 7) / 8;
    k_w<<<nb1, 256>>>(x, ef, idx, N);
    k_soft<<<(B + 31) / 32, 1024>>>(idx, N, B, nb1);

    int niter = (N + 255) / 256;
    int grid = niter < 148 ? niter : 148;
    int smem = (256 * STRIDE + 128 * STRIDE + 256 * 2 + 128 * 2 + 16) * 4;
    cudaFuncSetAttribute(k_mlp_mma, cudaFuncAttributeMaxDynamicSharedMemorySize, smem);
    k_mlp_mma<<<grid, 512, smem>>>(ef, idx, Wv, out, N, B, niter);
}

// round 10
// speedup vs baseline: 4.4862x; 1.4728x over previous
#include <cuda_runtime.h>
#include <cuda_fp16.h>
#include <math.h>
#include <stdint.h>

#define MAXN 400000
#define MAXB 10000
#define SH 136   // half-element row stride: 272B = 17 x 16B chunks -> conflict-free LDSM

// Scratch (static device globals; no allocations)
__device__ float g_ew[MAXN];
__device__ float g_anorm[MAXB];
__device__ float g_A[256];          // A0[0:128], A1[128:256]
__device__ float g_s[4];            // [0]=s0, [1]=s1
__device__ __half g_Wh[3][16384];   // fp16-rounded W1, W2, Wo

__device__ __forceinline__ float sspf(float x) {
    float ax = fabsf(x);
    float t = __expf(-ax);
    return fmaxf(x, 0.f) + __logf(1.f + t) - 0.69314718055994531f;
}

__device__ __forceinline__ uint32_t smem_u32(const void* p) {
    uint32_t a;
    asm("{ .reg .u64 t; cvta.to.shared.u64 t, %1; cvt.u32.u64 %0, t; }" : "=r"(a) : "l"(p));
    return a;
}

__device__ __forceinline__ void cpa16(uint32_t dst, const void* src) {
    asm volatile("cp.async.ca.shared.global [%0], [%1], 16;"
                 :: "r"(dst), "l"(__cvta_generic_to_global(src)) : "memory");
}
#define CP_COMMIT() asm volatile("cp.async.commit_group;" ::: "memory")
#define CP_WAIT0()  asm volatile("cp.async.wait_group 0;" ::: "memory")

__device__ __forceinline__ void ldsm4(uint32_t r[4], uint32_t addr) {
    asm volatile("ldmatrix.sync.aligned.m8n8.x4.shared.b16 {%0,%1,%2,%3}, [%4];"
                 : "=r"(r[0]), "=r"(r[1]), "=r"(r[2]), "=r"(r[3]) : "r"(addr));
}

__device__ __forceinline__ void mmaf16(float d[4], const uint32_t a[4], const uint32_t b[2]) {
    asm volatile(
        "mma.sync.aligned.m16n8k16.row.col.f32.f16.f16.f32 "
        "{%0,%1,%2,%3}, {%4,%5,%6,%7}, {%8,%9}, {%0,%1,%2,%3};"
        : "+f"(d[0]), "+f"(d[1]), "+f"(d[2]), "+f"(d[3])
        : "r"(a[0]), "r"(a[1]), "r"(a[2]), "r"(a[3]), "r"(b[0]), "r"(b[1]));
}

// 128x128x128 GEMM phase: warp computes 32x32 tile at (mb, nb).
// su (activations, half) and sw (weights, half) both [row][k], stride SH halves.
// A ldsm x4 -> {a0,a1,a2,a3}: rows(+0/+8) x k(+0/+8): row_off = lane&8, col_off = lane&16
// B ldsm x4 -> {b(nf)0, b(nf)1, b(nf+1)0, b(nf+1)1}: row_off = lane&16, col_off = lane&8
__device__ __forceinline__ void gemm32(uint32_t suB, uint32_t swB,
                                       int mb, int nb, int lane,
                                       float acc[2][4][4]) {
#pragma unroll
    for (int mf = 0; mf < 2; mf++)
#pragma unroll
        for (int nf = 0; nf < 4; nf++)
#pragma unroll
            for (int k = 0; k < 4; k++) acc[mf][nf][k] = 0.f;

    const int i = lane & 7;
    const uint32_t aadr = suB + 2u * (uint32_t)((mb + i + ((lane & 8) ? 8 : 0)) * SH
                                                + ((lane & 16) ? 8 : 0));
    const uint32_t badr = swB + 2u * (uint32_t)((nb + i + ((lane & 16) ? 8 : 0)) * SH
                                                + ((lane & 8) ? 8 : 0));
#pragma unroll
    for (int kb = 0; kb < 8; kb++) {
        uint32_t a0[4], a1[4], b0[4], b1[4];
        ldsm4(a0, aadr + kb * 32);
        ldsm4(a1, aadr + 16 * SH * 2 + kb * 32);
        ldsm4(b0, badr + kb * 32);
        ldsm4(b1, badr + 16 * SH * 2 + kb * 32);
        mmaf16(acc[0][0], a0, b0 + 0);
        mmaf16(acc[0][1], a0, b0 + 2);
        mmaf16(acc[0][2], a0, b1 + 0);
        mmaf16(acc[0][3], a0, b1 + 2);
        mmaf16(acc[1][0], a1, b0 + 0);
        mmaf16(acc[1][1], a1, b0 + 2);
        mmaf16(acc[1][2], a1, b1 + 0);
        mmaf16(acc[1][3], a1, b1 + 2);
    }
}

// load one 128x128 fp16 weight tile into padded smem via cp.async (2048 16B chunks)
__device__ __forceinline__ void issueW(uint32_t swB, const __half* __restrict__ src, int tid) {
#pragma unroll
    for (int it = 0; it < 4; it++) {
        int t = it * 512 + tid;
        int n = t >> 4, k8 = (t & 15) << 3;
        cpa16(swB + 2u * (uint32_t)(n * SH + k8), src + n * 128 + k8);
    }
    CP_COMMIT();
}

// ---------------------------------------------------------------------------
// Launch 1: fused prep (A0/A1/s0/s1) + fp16-round of W1/W2/Wo.
// ---------------------------------------------------------------------------
__global__ void k_prep_round(const float* __restrict__ Wq, const float* __restrict__ bq,
                             const float* __restrict__ Wk,
                             const float* __restrict__ W1, const float* __restrict__ W2,
                             const float* __restrict__ Wo) {
    if (blockIdx.x == 0) {
        int j = threadIdx.x;
        if (j < 128) {
            float a0 = 0.f, a1 = 0.f;
            for (int f = 0; f < 128; f++) {
                float wq = Wq[f * 128 + j];
                a0 += wq * Wk[2 * f];
                a1 += wq * Wk[2 * f + 1];
            }
            g_A[j] = a0;
            g_A[128 + j] = a1;
        }
        int wid = threadIdx.x >> 5, lane = threadIdx.x & 31;
        if (wid < 2) {
            float s = 0.f;
            for (int l = lane; l < 128; l += 32) s += bq[l] * Wk[2 * l + wid];
#pragma unroll
            for (int o = 16; o > 0; o >>= 1) s += __shfl_xor_sync(0xffffffffu, s, o);
            if (lane == 0) g_s[wid] = s;
        }
    } else {
        int t = (blockIdx.x - 1) * 1024 + threadIdx.x;
        if (t < 16384) g_Wh[0][t] = __float2half_rn(W1[t]);
        else if (t < 32768) g_Wh[1][t - 16384] = __float2half_rn(W2[t - 16384]);
        else g_Wh[2][t - 32768] = __float2half_rn(Wo[t - 32768]);
    }
}

// ---------------------------------------------------------------------------
// Launch 2: ew[i] = exp(w[i] - 10)  (softmax ratio is shift-invariant, so a
// fixed shift replaces the global max; no extra pass over N needed)
// ---------------------------------------------------------------------------
__global__ void k_w(const float* __restrict__ x, const float* __restrict__ ef,
                    const int* __restrict__ idx, int N) {
    __shared__ float A0s[128], A1s[128];
    int t = threadIdx.x;
    if (t < 128) A0s[t] = g_A[t];
    else A1s[t - 128] = g_A[t];
    __syncthreads();

    int warp = t >> 5, lane = t & 31;
    int i = blockIdx.x * 8 + warp;
    if (i >= N) return;
    int b = idx[i];
    float v = ef[b];
    float e0 = fmaxf(v, 0.f), e1 = fmaxf(-v, 0.f);
    float en0 = e0 / fmaxf(e0, 1.f), en1 = e1 / fmaxf(e1, 1.f);
    float4 xv = ((const float4*)(x + (size_t)i * 128))[lane];
    int j = lane * 4;
    float dot = xv.x * (en0 * A0s[j] + en1 * A1s[j]) +
                xv.y * (en0 * A0s[j + 1] + en1 * A1s[j + 1]) +
                xv.z * (en0 * A0s[j + 2] + en1 * A1s[j + 2]) +
                xv.w * (en0 * A0s[j + 3] + en1 * A1s[j + 3]);
#pragma unroll
    for (int o = 16; o > 0; o >>= 1) dot += __shfl_xor_sync(0xffffffffu, dot, o);
    if (lane == 0) {
        float wv = (dot + en0 * g_s[0] + en1 * g_s[1]) * 0.08838834764831845f;
        g_ew[i] = expf(wv - 10.f);
    }
}

// ---------------------------------------------------------------------------
// Launch 3: per-molecule segment sums (idx sorted; one warp per molecule)
// ---------------------------------------------------------------------------
__device__ __forceinline__ int lbound(const int* __restrict__ a, int n, int v) {
    int lo = 0, hi = n;
    while (lo < hi) {
        int m = (lo + hi) >> 1;
        if (a[m] < v) lo = m + 1;
        else hi = m;
    }
    return lo;
}

__global__ void k_seg(const int* __restrict__ idx, int N, int B) {
    int gw = (blockIdx.x * blockDim.x + threadIdx.x) >> 5;
    int lane = threadIdx.x & 31;
    if (gw >= B) return;
    int lo = lbound(idx, N, gw);
    int hi = lbound(idx, N, gw + 1);
    float s = 0.f;
    for (int i = lo + lane; i < hi; i += 32) s += g_ew[i];
#pragma unroll
    for (int o = 16; o > 0; o >>= 1) s += __shfl_xor_sync(0xffffffffu, s, o);
    if (lane == 0) g_anorm[gw] = s;
}

// ---------------------------------------------------------------------------
// Launch 4: persistent fused MLP, fp16 mma + ldmatrix, 128-row tiles,
// 2 CTAs/SM (regs capped at 64 via launch bounds).
// smem bytes: su[128*SH*2]=34816 | wbuf[128*SH*2]=34816 | sp,sq[128f each] |
//             swx,swy[128f each] | sred[16f]  => 71744 B/CTA
// ---------------------------------------------------------------------------
__global__ void __launch_bounds__(512, 2)
k_mlp_mma(const float* __restrict__ ef, const int* __restrict__ idx,
          const float* __restrict__ Wv, float* __restrict__ out,
          int N, int B, int niter) {
    extern __shared__ char smem[];
    __half* su = (__half*)smem;                    // 128 x SH halves
    __half* wb = (__half*)(smem + 34816);          // 128 x SH halves
    float* sp = (float*)(smem + 69632);
    float* sq = sp + 128;
    float* swx = sq + 128;
    float* swy = swx + 128;
    float* sred = swy + 128;

    const uint32_t suB = smem_u32(smem);
    const uint32_t wbB = suB + 34816u;

    const int tid = threadIdx.x;
    const int lane = tid & 31, wid = tid >> 5;
    const int mb = (wid >> 2) * 32, nb = (wid & 3) * 32;
    const int lq = lane >> 2, lr = lane & 3;

    if (tid < 128) {
        float2 wv = ((const float2*)Wv)[tid];
        swx[tid] = wv.x;
        swy[tid] = wv.y;
    }

    // deterministic per-CTA sum S = sum(anorm)
    {
        float s = 0.f;
        for (int i = tid; i < B; i += 512) s += g_anorm[i];
#pragma unroll
        for (int o = 16; o > 0; o >>= 1) s += __shfl_xor_sync(0xffffffffu, s, o);
        if (lane == 0) sred[wid] = s;
    }
    __syncthreads();
    float Sg = 0.f;
#pragma unroll
    for (int k = 0; k < 16; k++) Sg += sred[k];
    const float epsS = 1e-8f * Sg;

    issueW(wbB, g_Wh[0], tid);  // prologue: W1

    float acc[2][4][4];

    for (int iter = blockIdx.x; iter < niter; iter += gridDim.x) {
        const int row0 = iter * 128;

        if (tid < 128) {
            int i = row0 + tid;
            float pc = 0.f, qc = 0.f;
            if (i < N) {
                int b = idx[i];
                float v = ef[b];
                float c = g_ew[i] / (g_anorm[b] + epsS);
                pc = c * fmaxf(v, 0.f);
                qc = c * fmaxf(-v, 0.f);
            }
            sp[tid] = pc;
            sq[tid] = qc;
        }
        __syncthreads();

        // stage 0: u = fp16(ssp(x)), x = p[r]*wx[c] + q[r]*wy[c]; 8 halves/thread/it
#pragma unroll
        for (int it = 0; it < 4; it++) {
            int f = it * 512 + tid;
            int r = f >> 4, c8 = (f & 15) << 3;
            float pr = sp[r], qr = sq[r];
            __half2 h[4];
#pragma unroll
            for (int j = 0; j < 4; j++) {
                float v0 = sspf(pr * swx[c8 + 2 * j] + qr * swy[c8 + 2 * j]);
                float v1 = sspf(pr * swx[c8 + 2 * j + 1] + qr * swy[c8 + 2 * j + 1]);
                h[j] = __floats2half2_rn(v0, v1);
            }
            *(uint4*)(su + r * SH + c8) = *(uint4*)h;
        }
        CP_WAIT0();  // W1 ready
        __syncthreads();

        // GEMM1: D = u @ W1^T
        gemm32(suB, wbB, mb, nb, lane, acc);
        __syncthreads();

        issueW(wbB, g_Wh[1], tid);  // W2 (overlaps epi1)

        // epi1: u = fp16(ssp(D))
#pragma unroll
        for (int mf = 0; mf < 2; mf++) {
            int r = mb + mf * 16 + lq;
#pragma unroll
            for (int nf = 0; nf < 4; nf++) {
                int c = nb + nf * 8 + 2 * lr;
                *(__half2*)(su + r * SH + c) =
                    __floats2half2_rn(sspf(acc[mf][nf][0]), sspf(acc[mf][nf][1]));
                *(__half2*)(su + (r + 8) * SH + c) =
                    __floats2half2_rn(sspf(acc[mf][nf][2]), sspf(acc[mf][nf][3]));
            }
        }
        CP_WAIT0();  // W2 ready
        __syncthreads();

        // GEMM2: D = u @ W2^T
        gemm32(suB, wbB, mb, nb, lane, acc);
        __syncthreads();

        issueW(wbB, g_Wh[2], tid);  // Wo (overlaps epi2)

        // epi2: u = fp16(ssp(x + D)), x regenerated
#pragma unroll
        for (int mf = 0; mf < 2; mf++) {
            int r = mb + mf * 16 + lq;
            float p0 = sp[r], q0 = sq[r];
            float p1 = sp[r + 8], q1 = sq[r + 8];
#pragma unroll
            for (int nf = 0; nf < 4; nf++) {
                int c = nb + nf * 8 + 2 * lr;
                float wxa = swx[c], wxb = swx[c + 1];
                float wya = swy[c], wyb = swy[c + 1];
                *(__half2*)(su + r * SH + c) = __floats2half2_rn(
                    sspf(p0 * wxa + q0 * wya + acc[mf][nf][0]),
                    sspf(p0 * wxb + q0 * wyb + acc[mf][nf][1]));
                *(__half2*)(su + (r + 8) * SH + c) = __floats2half2_rn(
                    sspf(p1 * wxa + q1 * wya + acc[mf][nf][2]),
                    sspf(p1 * wxb + q1 * wyb + acc[mf][nf][3]));
            }
        }
        CP_WAIT0();  // Wo ready
        __syncthreads();

        // GEMM3: D = u @ Wo^T
        gemm32(suB, wbB, mb, nb, lane, acc);
        __syncthreads();

        issueW(wbB, g_Wh[0], tid);  // next iteration's W1

        // direct global stores
#pragma unroll
        for (int mf = 0; mf < 2; mf++) {
            int r = row0 + mb + mf * 16 + lq;
#pragma unroll
            for (int nf = 0; nf < 4; nf++) {
                int c = nb + nf * 8 + 2 * lr;
                if (r < N)
                    *(float2*)(out + (size_t)r * 128 + c) =
                        make_float2(acc[mf][nf][0], acc[mf][nf][1]);
                if (r + 8 < N)
                    *(float2*)(out + (size_t)(r + 8) * 128 + c) =
                        make_float2(acc[mf][nf][2], acc[mf][nf][3]);
            }
        }
        __syncthreads();  // su/sp safe to overwrite next iteration
    }
}

// ---------------------------------------------------------------------------
extern "C" void kernel_launch(void* const* d_in, const int* in_sizes, int n_in,
                              void* d_out, int out_size) {
    const float* x   = (const float*)d_in[0];
    const float* ef  = (const float*)d_in[1];
    const int*   idx = (const int*)d_in[2];
    const float* Wq  = (const float*)d_in[3];
    const float* bq  = (const float*)d_in[4];
    const float* Wk  = (const float*)d_in[5];
    const float* Wv  = (const float*)d_in[6];
    const float* W1  = (const float*)d_in[7];
    const float* W2  = (const float*)d_in[8];
    const float* Wo  = (const float*)d_in[9];
    float* out = (float*)d_out;

    int B = in_sizes[1];
    int N = in_sizes[2];

    k_prep_round<<<49, 1024>>>(Wq, bq, Wk, W1, W2, Wo);

    k_w<<<(N + 7) / 8, 256>>>(x, ef, idx, N);
    k_seg<<<(B + 7) / 8, 256>>>(idx, N, B);

    int niter = (N + 127) / 128;
    int grid = niter < 296 ? niter : 296;
    cudaFuncSetAttribute(k_mlp_mma, cudaFuncAttributeMaxDynamicSharedMemorySize, 71744);
    k_mlp_mma<<<grid, 512, 71744>>>(ef, idx, Wv, out, N, B, niter);
}